// round 16
// baseline (speedup 1.0000x reference)
#include <cuda_runtime.h>
#include <cstddef>

#define BATCH 8192

typedef unsigned long long u64;

__device__ __forceinline__ u64 pk2(float lo, float hi) {
    u64 r; asm("mov.b64 %0, {%1,%2};" : "=l"(r) : "f"(lo), "f"(hi)); return r;
}
__device__ __forceinline__ void upk2(u64 v, float& lo, float& hi) {
    asm("mov.b64 {%0,%1}, %2;" : "=f"(lo), "=f"(hi) : "l"(v));
}
__device__ __forceinline__ void ffma2(u64& d, u64 a, u64 b) {
    asm("fma.rn.f32x2 %0, %1, %2, %0;" : "+l"(d) : "l"(a), "l"(b));
}

// ---------------- scratch ----------------
__device__ float g_h1[BATCH * 32 * 144];
__device__ float g_h2[BATCH * 64 * 36];
__device__ float g_h3[BATCH * 1152];
__device__ float g_scores[BATCH * 1024];  // enc split-K scratch [4][8192][128]
__device__ float g_zq[BATCH * 128];
__device__ float g_d1[BATCH * 64 * 9];    // COMPACT dct1 out [B,64,3,3]
__device__ float g_d2[BATCH * 32 * 36];   // COMPACT dct2 out [B,32,6,6]
__device__ float g_cnorm[1024];
__device__ float g_M[576 * 128];
__device__ float g_cv[576];
__device__ float g_w2T[288 * 64];        // conv2 weights, [tap*64 + oc]
__device__ float g_pv[16 * BATCH];       // argmin partial values [colblk][img]
__device__ int   g_pi[16 * BATCH];       // argmin partial indices

// ================= prep: conv2 weight transpose + codebook norms =================
__global__ __launch_bounds__(256) void k_prep(const float* __restrict__ c2w,
                                              const float* __restrict__ cb) {
    int idx = blockIdx.x * 256 + threadIdx.x;
    if (idx < 288 * 64) {
        int k = idx >> 6, oc = idx & 63;
        g_w2T[idx] = c2w[oc * 288 + k];
    }
    if (idx < 1024) {
        float s = 0.f;
        const float* c = cb + (size_t)idx * 128;
#pragma unroll 8
        for (int k = 0; k < 128; k++) s = fmaf(c[k], c[k], s);
        g_cnorm[idx] = s;
    }
}

// ================= conv1 (1->32, 24x24) + relu + pool (R11 version) =================
__global__ __launch_bounds__(256) void k_conv1(const float* __restrict__ x,
                                               const float* __restrict__ w,
                                               const float* __restrict__ b) {
    __shared__ float sIn[26 * 26];
    __shared__ float sW[32 * 9];
    __shared__ float sB[32];
    int img = blockIdx.x;
    int tid = threadIdx.x;
    for (int i = tid; i < 26 * 26; i += 256) sIn[i] = 0.f;
    for (int i = tid; i < 288; i += 256) sW[i] = w[i];
    if (tid < 32) sB[tid] = b[tid];
    __syncthreads();
    const float* xi = x + (size_t)img * 576;
    for (int i = tid; i < 576; i += 256) {
        int y = i / 24, xx = i - y * 24;
        sIn[(y + 1) * 26 + xx + 1] = xi[i];
    }
    __syncthreads();
    int c = tid >> 3;
    float wr[9];
#pragma unroll
    for (int k = 0; k < 9; k++) wr[k] = sW[c * 9 + k];
    float bias = sB[c];
    float* outp = g_h1 + (size_t)img * 32 * 144 + (size_t)c * 144;
    for (int p = (tid & 7); p < 144; p += 8) {
        int py = p / 12, px = p - py * 12;
        float in4[4][4];
#pragma unroll
        for (int dy = 0; dy < 4; dy++)
#pragma unroll
            for (int dx = 0; dx < 4; dx++)
                in4[dy][dx] = sIn[(2 * py + dy) * 26 + 2 * px + dx];
        float m = 0.f;
#pragma unroll
        for (int dy = 0; dy < 2; dy++)
#pragma unroll
            for (int dx = 0; dx < 2; dx++) {
                float s = bias;
#pragma unroll
                for (int ky = 0; ky < 3; ky++)
#pragma unroll
                    for (int kx = 0; kx < 3; kx++)
                        s = fmaf(in4[dy + ky][dx + kx], wr[ky * 3 + kx], s);
                m = fmaxf(m, s);
            }
        outp[p] = m;
    }
}

// ================= conv2 (32->64) + relu + pool (R15 version — measured best) =======
#define C2TAPS(KY, TOP, BOT)                                                     \
    {                                                                            \
        _Pragma("unroll")                                                        \
        for (int kx = 0; kx < 3; kx++) {                                         \
            ulonglong2 wa = *reinterpret_cast<const ulonglong2*>(                \
                swoct + (ic * 9 + (KY) * 3 + kx) * 32);                          \
            u64 w01 = wa.x, w23 = wa.y;                                          \
            ffma2(acc2[0][0], w01, TOP[kx]);     ffma2(acc2[0][1], w23, TOP[kx]);\
            ffma2(acc2[1][0], w01, TOP[kx + 1]); ffma2(acc2[1][1], w23, TOP[kx + 1]);\
            ffma2(acc2[2][0], w01, BOT[kx]);     ffma2(acc2[2][1], w23, BOT[kx]);\
            ffma2(acc2[3][0], w01, BOT[kx + 1]); ffma2(acc2[3][1], w23, BOT[kx + 1]);\
        }                                                                        \
    }

#define LOADROW4(DST, PTR)                                                       \
    {                                                                            \
        float2 q0 = *reinterpret_cast<const float2*>(PTR);                       \
        float2 q1 = *reinterpret_cast<const float2*>((PTR) + 2);                 \
        DST[0] = pk2(q0.x, q0.x); DST[1] = pk2(q0.y, q0.y);                      \
        DST[2] = pk2(q1.x, q1.x); DST[3] = pk2(q1.y, q1.y);                      \
    }

__global__ __launch_bounds__(576, 2) void k_conv2(const float* __restrict__ b) {
    extern __shared__ float sm[];
    float* sIn = sm;               // 2 * 6272 = 12544
    float* sW  = sm + 12544;       // 288 taps * 32 oc = 9216
    float* sB  = sW + 9216;        // 64
    int blk = blockIdx.x;
    int tid = threadIdx.x;
    for (int i = tid; i < 12544; i += 576) sIn[i] = 0.f;
    if (tid < 64) sB[tid] = b[tid];
    __syncthreads();
    for (int i = tid; i < 2 * 32 * 144; i += 576) {
        int iml = i / 4608, r = i - iml * 4608;
        int c = r / 144, rr = r - c * 144;
        int y = rr / 12, xx = rr - y * 12;
        sIn[iml * 6272 + c * 196 + (y + 1) * 14 + xx + 1] =
            g_h1[(size_t)(blk * 2 + iml) * 4608 + r];
    }
    __syncthreads();
    int octile = tid / 72;
    int local = tid - octile * 72;
    int iml = local / 36;
    int p = local - iml * 36;
    int py = p / 6, px = p - py * 6;
    int y0 = 2 * py, x0 = 2 * px;
    const float* sbase = sIn + iml * 6272 + y0 * 14 + x0;
    const float* swoct = sW + octile * 4;
    float* outp = g_h2 + (size_t)(blk * 2 + iml) * 64 * 36;
    for (int chunk = 0; chunk < 2; chunk++) {
        __syncthreads();
        for (int i = tid; i < 288 * 32; i += 576)
            sW[i] = g_w2T[((i >> 5) << 6) + (chunk << 5) + (i & 31)];
        __syncthreads();
        u64 acc2[4][2];
#pragma unroll
        for (int q = 0; q < 4; q++) { acc2[q][0] = 0ULL; acc2[q][1] = 0ULL; }
        for (int ic = 0; ic < 32; ic++) {
            const float* sip = sbase + ic * 196;
            u64 ra[4], rb[4];
            LOADROW4(ra, sip)
            LOADROW4(rb, sip + 14)
            C2TAPS(0, ra, rb)
            LOADROW4(ra, sip + 28)
            C2TAPS(1, rb, ra)
            LOADROW4(rb, sip + 42)
            C2TAPS(2, ra, rb)
        }
#pragma unroll
        for (int j = 0; j < 2; j++) {
            float l0, h0, l1, h1, l2, h2, l3, h3;
            upk2(acc2[0][j], l0, h0); upk2(acc2[1][j], l1, h1);
            upk2(acc2[2][j], l2, h2); upk2(acc2[3][j], l3, h3);
            int oc = chunk * 32 + octile * 4 + 2 * j;
            float mlo = fmaxf(fmaxf(l0, l1), fmaxf(l2, l3)) + sB[oc];
            float mhi = fmaxf(fmaxf(h0, h1), fmaxf(h2, h3)) + sB[oc + 1];
            outp[oc * 36 + p] = fmaxf(mlo, 0.f);
            outp[(oc + 1) * 36 + p] = fmaxf(mhi, 0.f);
        }
    }
}

// ================= conv3 (64->128) + relu + pool (R15 version) =================
__global__ __launch_bounds__(576) void k_conv3(const float* __restrict__ w,
                                               const float* __restrict__ b) {
    extern __shared__ float sm[];
    float* sIn = sm;               // 8 * 4096 = 32768
    float* sW  = sm + 32768;       // 576 taps * pitch 36 = 20736
    float* sB  = sW + 20736;       // 128
    int blk = blockIdx.x;
    int tid = threadIdx.x;
    for (int i = tid; i < 32768; i += 576) sIn[i] = 0.f;
    if (tid < 128) sB[tid] = b[tid];
    __syncthreads();
    for (int i = tid; i < 8 * 64 * 36; i += 576) {
        int im = i / 2304;
        int r = i - im * 2304;
        int c = r / 36, rr = r - c * 36;
        int y = rr / 6, xx = rr - y * 6;
        sIn[im * 4096 + c * 64 + (y + 1) * 8 + xx + 1] = g_h2[(size_t)(blk * 8 + im) * 2304 + r];
    }
    int im = tid / 72;
    int r = tid - im * 72;
    int octile = r & 7;
    int p = r >> 3;
    int py = p / 3, px = p - py * 3;
    int y0 = 2 * py, x0 = 2 * px;
    const float* sbase = sIn + im * 4096 + y0 * 8 + x0;
    float* outp = g_h3 + (size_t)(blk * 8 + im) * 1152;
    for (int chunk = 0; chunk < 4; chunk++) {
        __syncthreads();
        for (int i = tid; i < 32 * 576; i += 576) {
            int ocl = i / 576, kk = i - ocl * 576;
            sW[kk * 36 + ocl] = w[(chunk * 32 + ocl) * 576 + kk];
        }
        __syncthreads();
        u64 acc2[4][2];
#pragma unroll
        for (int q = 0; q < 4; q++) { acc2[q][0] = 0ULL; acc2[q][1] = 0ULL; }
        for (int ic = 0; ic < 64; ic++) {
            const float* sip = sbase + ic * 64;
            u64 pin[4][4];
#pragma unroll
            for (int dy = 0; dy < 4; dy++) {
                float2 q0 = *reinterpret_cast<const float2*>(sip + dy * 8);
                float2 q1 = *reinterpret_cast<const float2*>(sip + dy * 8 + 2);
                pin[dy][0] = pk2(q0.x, q0.x); pin[dy][1] = pk2(q0.y, q0.y);
                pin[dy][2] = pk2(q1.x, q1.x); pin[dy][3] = pk2(q1.y, q1.y);
            }
#pragma unroll
            for (int k = 0; k < 9; k++) {
                int ky = k / 3, kx = k - ky * 3;
                const u64* wq = reinterpret_cast<const u64*>(sW + (ic * 9 + k) * 36) + octile * 2;
                u64 w01 = wq[0], w23 = wq[1];
                ffma2(acc2[0][0], w01, pin[ky][kx]);         ffma2(acc2[0][1], w23, pin[ky][kx]);
                ffma2(acc2[1][0], w01, pin[ky][kx + 1]);     ffma2(acc2[1][1], w23, pin[ky][kx + 1]);
                ffma2(acc2[2][0], w01, pin[ky + 1][kx]);     ffma2(acc2[2][1], w23, pin[ky + 1][kx]);
                ffma2(acc2[3][0], w01, pin[ky + 1][kx + 1]); ffma2(acc2[3][1], w23, pin[ky + 1][kx + 1]);
            }
        }
#pragma unroll
        for (int j = 0; j < 2; j++) {
            float l0, h0, l1, h1, l2, h2, l3, h3;
            upk2(acc2[0][j], l0, h0); upk2(acc2[1][j], l1, h1);
            upk2(acc2[2][j], l2, h2); upk2(acc2[3][j], l3, h3);
            int oc = chunk * 32 + octile * 4 + 2 * j;
            float mlo = fmaxf(fmaxf(l0, l1), fmaxf(l2, l3)) + sB[oc];
            float mhi = fmaxf(fmaxf(h0, h1), fmaxf(h2, h3)) + sB[oc + 1];
            outp[oc * 9 + p] = fmaxf(mlo, 0.f);
            outp[(oc + 1) * 9 + p] = fmaxf(mhi, 0.f);
        }
    }
}

// ================= enc FC GEMM, split-K x4 over gridDim.z =================
__global__ __launch_bounds__(256) void k_gemm_enc_sk(const float* __restrict__ A,
                                                     const float* __restrict__ Bm) {
    __shared__ float As[16][68];
    __shared__ float Bs[16][68];
    int m0 = blockIdx.x * 64;
    int n0 = blockIdx.y * 64;
    int s  = blockIdx.z;
    int tid = threadIdx.x;
    int lr = tid >> 2;
    int lk = (tid & 3) << 2;
    int tx = tid & 15, ty = tid >> 4;
    u64 acc2[4][2];
#pragma unroll
    for (int i = 0; i < 4; i++) { acc2[i][0] = 0ULL; acc2[i][1] = 0ULL; }
    const float* aPtr = A + (size_t)(m0 + lr) * 1152 + s * 288 + lk;
    const float* bPtr = Bm + (size_t)(n0 + lr) * 1152 + s * 288 + lk;
    for (int k0 = 0; k0 < 288; k0 += 16) {
        float4 av = *(const float4*)(aPtr + k0);
        float4 bv = *(const float4*)(bPtr + k0);
        __syncthreads();
        As[lk + 0][lr] = av.x; As[lk + 1][lr] = av.y; As[lk + 2][lr] = av.z; As[lk + 3][lr] = av.w;
        Bs[lk + 0][lr] = bv.x; Bs[lk + 1][lr] = bv.y; Bs[lk + 2][lr] = bv.z; Bs[lk + 3][lr] = bv.w;
        __syncthreads();
#pragma unroll
        for (int kk = 0; kk < 16; kk++) {
            float4 a = *(const float4*)&As[kk][ty * 4];
            float4 bq = *(const float4*)&Bs[kk][tx * 4];
            u64 pb0 = pk2(bq.x, bq.y), pb1 = pk2(bq.z, bq.w);
            float ar[4] = {a.x, a.y, a.z, a.w};
#pragma unroll
            for (int i = 0; i < 4; i++) {
                u64 pa = pk2(ar[i], ar[i]);
                ffma2(acc2[i][0], pb0, pa);
                ffma2(acc2[i][1], pb1, pa);
            }
        }
    }
    float* outp = g_scores + (size_t)s * BATCH * 128;
#pragma unroll
    for (int i = 0; i < 4; i++) {
        int m = m0 + ty * 4 + i;
        float v[4];
        upk2(acc2[i][0], v[0], v[1]);
        upk2(acc2[i][1], v[2], v[3]);
#pragma unroll
        for (int j = 0; j < 4; j++) {
            int n = n0 + tx * 4 + j;
            outp[(size_t)m * 128 + n] = v[j];
        }
    }
}

// ================= scores GEMM with fused z-reduction + argmin partials (R14) ========
__global__ __launch_bounds__(256) void k_scores(const float* __restrict__ cbm,
                                                const float* __restrict__ encb) {
    __shared__ float As[16][68];
    __shared__ float Bs[16][68];
    __shared__ float sCn[64];
    __shared__ float sBias[128];
    int m0 = blockIdx.x * 64;
    int n0 = blockIdx.y * 64;
    int tid = threadIdx.x;
    if (tid < 64) sCn[tid] = g_cnorm[n0 + tid];
    if (tid < 128) sBias[tid] = encb[tid];
    __syncthreads();
    int lr = tid >> 2;
    int lk = (tid & 3) << 2;
    int tx = tid & 15, ty = tid >> 4;
    u64 acc2[4][2];
#pragma unroll
    for (int i = 0; i < 4; i++) { acc2[i][0] = 0ULL; acc2[i][1] = 0ULL; }
    const size_t S = (size_t)BATCH * 128;
    const float* aPtr = g_scores + (size_t)(m0 + lr) * 128 + lk;
    const float* bPtr = cbm + (size_t)(n0 + lr) * 128 + lk;
    for (int k0 = 0; k0 < 128; k0 += 16) {
        float4 p0 = *(const float4*)(aPtr + k0);
        float4 p1 = *(const float4*)(aPtr + k0 + S);
        float4 p2 = *(const float4*)(aPtr + k0 + 2 * S);
        float4 p3 = *(const float4*)(aPtr + k0 + 3 * S);
        float4 av;
        av.x = (p0.x + p1.x) + (p2.x + p3.x) + sBias[lk + k0 + 0];
        av.y = (p0.y + p1.y) + (p2.y + p3.y) + sBias[lk + k0 + 1];
        av.z = (p0.z + p1.z) + (p2.z + p3.z) + sBias[lk + k0 + 2];
        av.w = (p0.w + p1.w) + (p2.w + p3.w) + sBias[lk + k0 + 3];
        float4 bv = *(const float4*)(bPtr + k0);
        __syncthreads();
        As[lk + 0][lr] = av.x; As[lk + 1][lr] = av.y; As[lk + 2][lr] = av.z; As[lk + 3][lr] = av.w;
        Bs[lk + 0][lr] = bv.x; Bs[lk + 1][lr] = bv.y; Bs[lk + 2][lr] = bv.z; Bs[lk + 3][lr] = bv.w;
        __syncthreads();
#pragma unroll
        for (int kk = 0; kk < 16; kk++) {
            float4 a = *(const float4*)&As[kk][ty * 4];
            float4 bq = *(const float4*)&Bs[kk][tx * 4];
            u64 pb0 = pk2(bq.x, bq.y), pb1 = pk2(bq.z, bq.w);
            float ar[4] = {a.x, a.y, a.z, a.w};
#pragma unroll
            for (int i = 0; i < 4; i++) {
                u64 pa = pk2(ar[i], ar[i]);
                ffma2(acc2[i][0], pb0, pa);
                ffma2(acc2[i][1], pb1, pa);
            }
        }
    }
    int cbi = blockIdx.y;
#pragma unroll
    for (int i = 0; i < 4; i++) {
        int m = m0 + ty * 4 + i;
        float v[4];
        upk2(acc2[i][0], v[0], v[1]);
        upk2(acc2[i][1], v[2], v[3]);
        float best = sCn[tx * 4 + 0] - 2.f * v[0];
        int bidx = n0 + tx * 4 + 0;
#pragma unroll
        for (int j = 1; j < 4; j++) {
            float d = sCn[tx * 4 + j] - 2.f * v[j];
            if (d < best) { best = d; bidx = n0 + tx * 4 + j; }
        }
#pragma unroll
        for (int s = 8; s > 0; s >>= 1) {
            float v2 = __shfl_down_sync(0xffffffffu, best, s, 16);
            int i2 = __shfl_down_sync(0xffffffffu, bidx, s, 16);
            if (v2 < best || (v2 == best && i2 < bidx)) { best = v2; bidx = i2; }
        }
        if (tx == 0) {
            g_pv[(size_t)cbi * BATCH + m] = best;
            g_pi[(size_t)cbi * BATCH + m] = bidx;
        }
    }
}

// ================= final argmin over 16 partials + gather z_q ====================
__global__ __launch_bounds__(256) void k_argmin_final(const float* __restrict__ cb) {
    int tid = threadIdx.x;
    int wid = tid >> 5;
    int lane = tid & 31;
    int img = blockIdx.x * 8 + wid;
    float best = 3.4e38f;
    int bidx = 0x7fffffff;
    if (lane < 16) {
        best = g_pv[(size_t)lane * BATCH + img];
        bidx = g_pi[(size_t)lane * BATCH + img];
    }
#pragma unroll
    for (int s = 8; s > 0; s >>= 1) {
        float v2 = __shfl_down_sync(0xffffffffu, best, s, 16);
        int i2 = __shfl_down_sync(0xffffffffu, bidx, s, 16);
        if (v2 < best || (v2 == best && i2 < bidx)) { best = v2; bidx = i2; }
    }
    int idx = __shfl_sync(0xffffffffu, bidx, 0);
    const float4* src = reinterpret_cast<const float4*>(cb + (size_t)idx * 128);
    float4* dst = reinterpret_cast<float4*>(g_zq + (size_t)img * 128);
    dst[lane] = src[lane];
}

// ================= build fused M / cv — 3 independent FMA chains =================
__global__ __launch_bounds__(512) void k_buildM(const float* __restrict__ w1,
                                                const float* __restrict__ b1,
                                                const float* __restrict__ decw,
                                                const float* __restrict__ decb) {
    __shared__ float red[512];
    int row = blockIdx.x;
    int oc = row / 9, pp = row - oc * 9, py = pp / 3, px = pp - py * 3;
    int tid = threadIdx.x;
    int g = tid >> 7;
    int l = tid & 127;
    int qs[9];
    float vm[9];
#pragma unroll
    for (int t = 0; t < 9; t++) {
        int ky = t / 3, kx = t - ky * 3;
        int qy = py + ky - 1, qx = px + kx - 1;
        bool v = (qy >= 0 && qy < 3 && qx >= 0 && qx < 3);
        qs[t] = v ? qy * 3 + qx : 0;
        vm[t] = v ? 1.f : 0.f;
    }
    const float* wbase = w1 + oc * 9;
    float a0 = 0.f, a1 = 0.f, a2 = 0.f;   // 3 independent chains (t mod 3)
    for (int ic = g * 32; ic < (g + 1) * 32; ic++) {
        const float* dr = decw + (size_t)ic * 1152 + l;
        const float* wr = wbase + ic * 576;
#pragma unroll
        for (int t = 0; t < 9; t += 3) {
            a0 = fmaf(vm[t + 0] * wr[8 - (t + 0)], dr[(size_t)qs[t + 0] * 128], a0);
            a1 = fmaf(vm[t + 1] * wr[8 - (t + 1)], dr[(size_t)qs[t + 1] * 128], a1);
            a2 = fmaf(vm[t + 2] * wr[8 - (t + 2)], dr[(size_t)qs[t + 2] * 128], a2);
        }
    }
    red[tid] = (a0 + a1) + a2;
    __syncthreads();
    float msum = 0.f, ab = 0.f;
    if (tid < 128) {
        msum = red[tid] + red[tid + 128] + red[tid + 256] + red[tid + 384];
        const float* wr = wbase + tid * 576;
#pragma unroll
        for (int t = 0; t < 9; t++)
            ab = fmaf(vm[t] * wr[8 - t], decb[tid * 9 + qs[t]], ab);
    }
    __syncthreads();
    if (tid < 128) {
        g_M[row * 128 + tid] = msum;
        red[tid] = ab;
    }
    __syncthreads();
    for (int s = 64; s > 0; s >>= 1) {
        if (tid < s) red[tid] += red[tid + s];
        __syncthreads();
    }
    if (tid == 0) g_cv[row] = red[0] + b1[oc];
}

// ================= fused dec_fc+dct1 -> COMPACT d1c [B,64,3,3] =================
__global__ __launch_bounds__(256) void k_fc1() {
    __shared__ float As[16][68];
    __shared__ float Bs[16][68];
    int m0 = blockIdx.x * 64;
    int n0 = blockIdx.y * 64;
    int tid = threadIdx.x;
    int lr = tid >> 2;
    int lk = (tid & 3) << 2;
    int tx = tid & 15, ty = tid >> 4;
    u64 acc2[4][2];
#pragma unroll
    for (int i = 0; i < 4; i++) { acc2[i][0] = 0ULL; acc2[i][1] = 0ULL; }
    const float* aPtr = g_zq + (size_t)(m0 + lr) * 128 + lk;
    const float* bPtr = g_M + (size_t)(n0 + lr) * 128 + lk;
    for (int k0 = 0; k0 < 128; k0 += 16) {
        float4 av = *(const float4*)(aPtr + k0);
        float4 bv = *(const float4*)(bPtr + k0);
        __syncthreads();
        As[lk + 0][lr] = av.x; As[lk + 1][lr] = av.y; As[lk + 2][lr] = av.z; As[lk + 3][lr] = av.w;
        Bs[lk + 0][lr] = bv.x; Bs[lk + 1][lr] = bv.y; Bs[lk + 2][lr] = bv.z; Bs[lk + 3][lr] = bv.w;
        __syncthreads();
#pragma unroll
        for (int kk = 0; kk < 16; kk++) {
            float4 a = *(const float4*)&As[kk][ty * 4];
            float4 bq = *(const float4*)&Bs[kk][tx * 4];
            u64 pb0 = pk2(bq.x, bq.y), pb1 = pk2(bq.z, bq.w);
            float ar[4] = {a.x, a.y, a.z, a.w};
#pragma unroll
            for (int i = 0; i < 4; i++) {
                u64 pa = pk2(ar[i], ar[i]);
                ffma2(acc2[i][0], pb0, pa);
                ffma2(acc2[i][1], pb1, pa);
            }
        }
    }
#pragma unroll
    for (int i = 0; i < 4; i++) {
        int m = m0 + ty * 4 + i;
        float v[4];
        upk2(acc2[i][0], v[0], v[1]);
        upk2(acc2[i][1], v[2], v[3]);
#pragma unroll
        for (int j = 0; j < 4; j++) {
            int n = n0 + tx * 4 + j;
            float val = fmaxf(v[j] + g_cv[n], 0.f);
            g_d1[(size_t)m * 576 + n] = val;
        }
    }
}

// ================= dct2 (64->32) compact conv-transpose (R9 version) =================
__global__ __launch_bounds__(384, 2) void k_dct2(const float* __restrict__ w,
                                                 const float* __restrict__ b) {
    extern __shared__ float sm[];
    float* sIn = sm;                // 8 * 576 = 4608
    float* sW  = sm + 4608;         // 576 taps * pitch 36 = 20736 (flipped)
    float* sB  = sW + 20736;        // 32
    int blk = blockIdx.x;           // 1024
    int tid = threadIdx.x;
    for (int i = tid; i < 8 * 576; i += 384)
        sIn[i] = g_d1[(size_t)blk * 8 * 576 + i];
    for (int i = tid; i < 64 * 288; i += 384) {
        int ic = i / 288, r2 = i - ic * 288;
        int oc = r2 / 9, g = r2 - oc * 9;
        sW[(ic * 9 + 8 - g) * 36 + oc] = w[i];
    }
    if (tid < 32) sB[tid] = b[tid];
    __syncthreads();
    int im = tid / 48;
    int r = tid - im * 48;
    int octile = r & 7;
    int y = r >> 3;
    int sy = y & 1;
    int rtop = (y - 1) >> 1;
    const float* sip = sIn + im * 576;
    u64 acc2[6][2];
#pragma unroll
    for (int xq = 0; xq < 6; xq++) { acc2[xq][0] = 0ULL; acc2[xq][1] = 0ULL; }
    for (int ic = 0; ic < 64; ic++) {
        const float* ch = sip + ic * 9;
        u64 pinr[2][5];
#pragma unroll
        for (int rr = 0; rr < 2; rr++) {
            int row = rtop + rr;
            bool v = (row >= 0) && (row < 3);
            pinr[rr][0] = 0ULL;
            pinr[rr][4] = 0ULL;
#pragma unroll
            for (int c = 0; c < 3; c++) {
                float f = v ? ch[row * 3 + c] : 0.f;
                pinr[rr][c + 1] = pk2(f, f);
            }
        }
        const u64* rowp[3];
        rowp[0] = pinr[0];
        rowp[1] = sy ? pinr[0] : pinr[1];
        rowp[2] = pinr[1];
#pragma unroll
        for (int ky = 0; ky < 3; ky++) {
            const u64* prow = rowp[ky];
#pragma unroll
            for (int kx = 0; kx < 3; kx++) {
                const u64* wq = reinterpret_cast<const u64*>(sW + (ic * 9 + ky * 3 + kx) * 36) + octile * 2;
                u64 w01 = wq[0], w23 = wq[1];
#pragma unroll
                for (int xq = 0; xq < 6; xq++) {
                    int c = ((xq + kx - 1) >> 1) + 1;
                    ffma2(acc2[xq][0], w01, prow[c]);
                    ffma2(acc2[xq][1], w23, prow[c]);
                }
            }
        }
    }
#pragma unroll
    for (int j = 0; j < 2; j++) {
        int oc = octile * 4 + 2 * j;
        float blo = sB[oc], bhi = sB[oc + 1];
        float* olo = g_d2 + ((size_t)(blk * 8 + im) * 32 + oc) * 36 + y * 6;
        float* ohi = olo + 36;
#pragma unroll
        for (int xq = 0; xq < 6; xq++) {
            float vl, vh;
            upk2(acc2[xq][j], vl, vh);
            olo[xq] = fmaxf(vl + blo, 0.f);
            ohi[xq] = fmaxf(vh + bhi, 0.f);
        }
    }
}

// ================= dct3 (32->1) compact conv-transpose + up2 -> out (R9 version) =====
__global__ __launch_bounds__(192) void k_dct3(const float* __restrict__ w,
                                              const float* __restrict__ b,
                                              float* __restrict__ out) {
    extern __shared__ float sm[];
    float* sIn = sm;                // 8 * 1152 = 9216
    float* sW  = sm + 9216;         // 288
    int blk = blockIdx.x;           // 1024
    int tid = threadIdx.x;
    for (int i = tid; i < 8 * 1152; i += 192)
        sIn[i] = g_d2[(size_t)blk * 8 * 1152 + i];
    for (int i = tid; i < 288; i += 192) {
        int ic = i / 9, k = i - ic * 9;
        sW[ic * 9 + k] = w[ic * 9 + (8 - k)];
    }
    __syncthreads();
    float b0 = b[0];
    int im = tid / 24;
    int r = tid - im * 24;
    int y = r >> 1;
    int xh2 = (r & 1) * 3;
    int xh = (r & 1) * 6;
    int sy = y & 1;
    int rtop = (y - 1) >> 1;
    const float* sip = sIn + im * 1152;
    float acc[6];
#pragma unroll
    for (int xq = 0; xq < 6; xq++) acc[xq] = 0.f;
    for (int ic = 0; ic < 32; ic++) {
        const float* ch = sip + ic * 36;
        float pinr[2][8];
#pragma unroll
        for (int rr = 0; rr < 2; rr++) {
            int row = rtop + rr;
            bool v = (row >= 0) && (row < 6);
            pinr[rr][0] = 0.f;
            pinr[rr][7] = 0.f;
#pragma unroll
            for (int c = 0; c < 6; c++)
                pinr[rr][c + 1] = v ? ch[row * 6 + c] : 0.f;
        }
        const float* rowp[3];
        rowp[0] = pinr[0];
        rowp[1] = sy ? pinr[0] : pinr[1];
        rowp[2] = pinr[1];
#pragma unroll
        for (int ky = 0; ky < 3; ky++) {
            const float* prow = rowp[ky];
            float w3[3];
#pragma unroll
            for (int kx = 0; kx < 3; kx++) w3[kx] = sW[ic * 9 + ky * 3 + kx];
#pragma unroll
            for (int xq = 0; xq < 6; xq++)
#pragma unroll
                for (int kx = 0; kx < 3; kx++) {
                    int c = xh2 + ((xq + kx - 1) >> 1) + 1;
                    acc[xq] = fmaf(prow[c], w3[kx], acc[xq]);
                }
        }
    }
    float* o = out + (size_t)(blk * 8 + im) * 576;
#pragma unroll
    for (int xq = 0; xq < 6; xq++) {
        float v = fmaxf(acc[xq] + b0, 0.f);
        int gx = xh + xq;
        int rb = (2 * y) * 24 + 2 * gx;
        o[rb] = v; o[rb + 1] = v; o[rb + 24] = v; o[rb + 25] = v;
    }
}

// ================= launcher =================
extern "C" void kernel_launch(void* const* d_in, const int* in_sizes, int n_in,
                              void* d_out, int out_size) {
    (void)in_sizes; (void)n_in; (void)out_size;
    const float* x    = (const float*)d_in[0];
    const float* c1w  = (const float*)d_in[1];
    const float* c1b  = (const float*)d_in[2];
    const float* c2w  = (const float*)d_in[3];
    const float* c2b  = (const float*)d_in[4];
    const float* c3w  = (const float*)d_in[5];
    const float* c3b  = (const float*)d_in[6];
    const float* encw = (const float*)d_in[7];
    const float* encb = (const float*)d_in[8];
    const float* cb   = (const float*)d_in[9];
    const float* decw = (const float*)d_in[10];
    const float* decb = (const float*)d_in[11];
    const float* d1w  = (const float*)d_in[12];
    const float* d1b  = (const float*)d_in[13];
    const float* d2w  = (const float*)d_in[14];
    const float* d2b  = (const float*)d_in[15];
    const float* d3w  = (const float*)d_in[16];
    const float* d3b  = (const float*)d_in[17];
    float* out = (float*)d_out;

    cudaFuncSetAttribute(k_conv2, cudaFuncAttributeMaxDynamicSharedMemorySize, 87296);
    cudaFuncSetAttribute(k_conv3, cudaFuncAttributeMaxDynamicSharedMemorySize, 214528);
    cudaFuncSetAttribute(k_dct2,  cudaFuncAttributeMaxDynamicSharedMemorySize, 101504);
    cudaFuncSetAttribute(k_dct3,  cudaFuncAttributeMaxDynamicSharedMemorySize, 38016);

    float* p_h3;
    cudaGetSymbolAddress((void**)&p_h3, g_h3);

    k_prep<<<72, 256>>>(c2w, cb);
    k_conv1<<<BATCH, 256>>>(x, c1w, c1b);
    k_buildM<<<576, 512>>>(d1w, d1b, decw, decb);
    k_conv2<<<BATCH / 2, 576, 87296>>>(c2b);
    k_conv3<<<BATCH / 8, 576, 214528>>>(c3w, c3b);
    k_gemm_enc_sk<<<dim3(BATCH / 64, 2, 4), 256>>>(p_h3, encw);
    k_scores<<<dim3(BATCH / 64, 16), 256>>>(cb, encb);
    k_argmin_final<<<BATCH / 8, 256>>>(cb);
    k_fc1<<<dim3(BATCH / 64, 9), 256>>>();
    k_dct2<<<BATCH / 8, 384, 101504>>>(d2w, d2b);
    k_dct3<<<BATCH / 8, 192, 38016>>>(d3w, d3b, out);
}

// round 17
// speedup vs baseline: 1.0136x; 1.0136x over previous
#include <cuda_runtime.h>
#include <cstddef>

#define BATCH 8192

typedef unsigned long long u64;

__device__ __forceinline__ u64 pk2(float lo, float hi) {
    u64 r; asm("mov.b64 %0, {%1,%2};" : "=l"(r) : "f"(lo), "f"(hi)); return r;
}
__device__ __forceinline__ void upk2(u64 v, float& lo, float& hi) {
    asm("mov.b64 {%0,%1}, %2;" : "=f"(lo), "=f"(hi) : "l"(v));
}
__device__ __forceinline__ void ffma2(u64& d, u64 a, u64 b) {
    asm("fma.rn.f32x2 %0, %1, %2, %0;" : "+l"(d) : "l"(a), "l"(b));
}

// ---------------- scratch ----------------
__device__ float g_h1[BATCH * 32 * 144];
__device__ float g_h2[BATCH * 64 * 36];
__device__ float g_h3[BATCH * 1152];
__device__ float g_scores[BATCH * 1024];  // enc split-K scratch [4][8192][128]
__device__ float g_zq[BATCH * 128];
__device__ float g_d1[BATCH * 64 * 9];    // COMPACT dct1 out [B,64,3,3]
__device__ float g_d2[BATCH * 32 * 36];   // COMPACT dct2 out [B,32,6,6]
__device__ float g_cnorm[1024];
__device__ float g_M[576 * 128];
__device__ float g_cv[576];
__device__ float g_w2T[288 * 64];        // conv2 weights, [tap*64 + oc]
__device__ float g_pv[16 * BATCH];       // argmin partial values [colblk][img]
__device__ int   g_pi[16 * BATCH];       // argmin partial indices

// ================= conv1 (1->32) + relu + pool, with prep blocks appended ============
// blocks [0, 8192): conv1 per image. blocks [8192, 8264): prep (w2T transpose + cnorm).
__global__ __launch_bounds__(256) void k_conv1(const float* __restrict__ x,
                                               const float* __restrict__ w,
                                               const float* __restrict__ b,
                                               const float* __restrict__ c2w,
                                               const float* __restrict__ cb) {
    int tid = threadIdx.x;
    if (blockIdx.x >= BATCH) {
        int idx = (blockIdx.x - BATCH) * 256 + tid;
        if (idx < 288 * 64) {
            int k = idx >> 6, oc = idx & 63;
            g_w2T[idx] = c2w[oc * 288 + k];
        }
        if (idx < 1024) {
            float s = 0.f;
            const float* c = cb + (size_t)idx * 128;
#pragma unroll 8
            for (int k = 0; k < 128; k++) s = fmaf(c[k], c[k], s);
            g_cnorm[idx] = s;
        }
        return;
    }
    __shared__ float sIn[26 * 26];
    __shared__ float sW[32 * 9];
    __shared__ float sB[32];
    int img = blockIdx.x;
    for (int i = tid; i < 26 * 26; i += 256) sIn[i] = 0.f;
    for (int i = tid; i < 288; i += 256) sW[i] = w[i];
    if (tid < 32) sB[tid] = b[tid];
    __syncthreads();
    const float* xi = x + (size_t)img * 576;
    for (int i = tid; i < 576; i += 256) {
        int y = i / 24, xx = i - y * 24;
        sIn[(y + 1) * 26 + xx + 1] = xi[i];
    }
    __syncthreads();
    int c = tid >> 3;
    float wr[9];
#pragma unroll
    for (int k = 0; k < 9; k++) wr[k] = sW[c * 9 + k];
    float bias = sB[c];
    float* outp = g_h1 + (size_t)img * 32 * 144 + (size_t)c * 144;
    for (int p = (tid & 7); p < 144; p += 8) {
        int py = p / 12, px = p - py * 12;
        float in4[4][4];
#pragma unroll
        for (int dy = 0; dy < 4; dy++)
#pragma unroll
            for (int dx = 0; dx < 4; dx++)
                in4[dy][dx] = sIn[(2 * py + dy) * 26 + 2 * px + dx];
        float m = 0.f;
#pragma unroll
        for (int dy = 0; dy < 2; dy++)
#pragma unroll
            for (int dx = 0; dx < 2; dx++) {
                float s = bias;
#pragma unroll
                for (int ky = 0; ky < 3; ky++)
#pragma unroll
                    for (int kx = 0; kx < 3; kx++)
                        s = fmaf(in4[dy + ky][dx + kx], wr[ky * 3 + kx], s);
                m = fmaxf(m, s);
            }
        outp[p] = m;
    }
}

// ================= conv2 (32->64) + relu + pool, with buildM blocks appended =========
// blocks [0, 4096): conv2 (R15 path, unchanged). blocks [4096, 4672): buildM row.
#define C2TAPS(KY, TOP, BOT)                                                     \
    {                                                                            \
        _Pragma("unroll")                                                        \
        for (int kx = 0; kx < 3; kx++) {                                         \
            ulonglong2 wa = *reinterpret_cast<const ulonglong2*>(                \
                swoct + (ic * 9 + (KY) * 3 + kx) * 32);                          \
            u64 w01 = wa.x, w23 = wa.y;                                          \
            ffma2(acc2[0][0], w01, TOP[kx]);     ffma2(acc2[0][1], w23, TOP[kx]);\
            ffma2(acc2[1][0], w01, TOP[kx + 1]); ffma2(acc2[1][1], w23, TOP[kx + 1]);\
            ffma2(acc2[2][0], w01, BOT[kx]);     ffma2(acc2[2][1], w23, BOT[kx]);\
            ffma2(acc2[3][0], w01, BOT[kx + 1]); ffma2(acc2[3][1], w23, BOT[kx + 1]);\
        }                                                                        \
    }

#define LOADROW4(DST, PTR)                                                       \
    {                                                                            \
        float2 q0 = *reinterpret_cast<const float2*>(PTR);                       \
        float2 q1 = *reinterpret_cast<const float2*>((PTR) + 2);                 \
        DST[0] = pk2(q0.x, q0.x); DST[1] = pk2(q0.y, q0.y);                      \
        DST[2] = pk2(q1.x, q1.x); DST[3] = pk2(q1.y, q1.y);                      \
    }

__global__ __launch_bounds__(576, 2) void k_conv2(const float* __restrict__ b,
                                                  const float* __restrict__ w1,
                                                  const float* __restrict__ b1,
                                                  const float* __restrict__ decw,
                                                  const float* __restrict__ decb) {
    extern __shared__ float sm[];
    int tid = threadIdx.x;
    if (blockIdx.x >= 4096) {
        // ---- buildM path (576 threads; g<4 guard; same arithmetic as R16) ----
        float* red = sm;             // 576 floats
        int row = blockIdx.x - 4096;
        int oc = row / 9, pp = row - oc * 9, py = pp / 3, px = pp - py * 3;
        int g = tid >> 7;            // 0..4
        int l = tid & 127;
        int qs[9];
        float vm[9];
#pragma unroll
        for (int t = 0; t < 9; t++) {
            int ky = t / 3, kx = t - ky * 3;
            int qy = py + ky - 1, qx = px + kx - 1;
            bool v = (qy >= 0 && qy < 3 && qx >= 0 && qx < 3);
            qs[t] = v ? qy * 3 + qx : 0;
            vm[t] = v ? 1.f : 0.f;
        }
        const float* wbase = w1 + oc * 9;
        float a0 = 0.f, a1 = 0.f, a2 = 0.f;
        if (g < 4) {
            for (int ic = g * 32; ic < (g + 1) * 32; ic++) {
                const float* dr = decw + (size_t)ic * 1152 + l;
                const float* wr = wbase + ic * 576;
#pragma unroll
                for (int t = 0; t < 9; t += 3) {
                    a0 = fmaf(vm[t + 0] * wr[8 - (t + 0)], dr[(size_t)qs[t + 0] * 128], a0);
                    a1 = fmaf(vm[t + 1] * wr[8 - (t + 1)], dr[(size_t)qs[t + 1] * 128], a1);
                    a2 = fmaf(vm[t + 2] * wr[8 - (t + 2)], dr[(size_t)qs[t + 2] * 128], a2);
                }
            }
        }
        red[tid] = (a0 + a1) + a2;
        __syncthreads();
        float msum = 0.f, ab = 0.f;
        if (tid < 128) {
            msum = red[tid] + red[tid + 128] + red[tid + 256] + red[tid + 384];
            const float* wr = wbase + tid * 576;
#pragma unroll
            for (int t = 0; t < 9; t++)
                ab = fmaf(vm[t] * wr[8 - t], decb[tid * 9 + qs[t]], ab);
        }
        __syncthreads();
        if (tid < 128) {
            g_M[row * 128 + tid] = msum;
            red[tid] = ab;
        }
        __syncthreads();
        for (int s = 64; s > 0; s >>= 1) {
            if (tid < s) red[tid] += red[tid + s];
            __syncthreads();
        }
        if (tid == 0) g_cv[row] = red[0] + b1[oc];
        return;
    }
    // ---- conv2 path (R15, unchanged) ----
    float* sIn = sm;               // 2 * 6272 = 12544
    float* sW  = sm + 12544;       // 288 taps * 32 oc = 9216
    float* sB  = sW + 9216;        // 64
    int blk = blockIdx.x;
    for (int i = tid; i < 12544; i += 576) sIn[i] = 0.f;
    if (tid < 64) sB[tid] = b[tid];
    __syncthreads();
    for (int i = tid; i < 2 * 32 * 144; i += 576) {
        int iml = i / 4608, r = i - iml * 4608;
        int c = r / 144, rr = r - c * 144;
        int y = rr / 12, xx = rr - y * 12;
        sIn[iml * 6272 + c * 196 + (y + 1) * 14 + xx + 1] =
            g_h1[(size_t)(blk * 2 + iml) * 4608 + r];
    }
    __syncthreads();
    int octile = tid / 72;
    int local = tid - octile * 72;
    int iml = local / 36;
    int p = local - iml * 36;
    int py = p / 6, px = p - py * 6;
    int y0 = 2 * py, x0 = 2 * px;
    const float* sbase = sIn + iml * 6272 + y0 * 14 + x0;
    const float* swoct = sW + octile * 4;
    float* outp = g_h2 + (size_t)(blk * 2 + iml) * 64 * 36;
    for (int chunk = 0; chunk < 2; chunk++) {
        __syncthreads();
        for (int i = tid; i < 288 * 32; i += 576)
            sW[i] = g_w2T[((i >> 5) << 6) + (chunk << 5) + (i & 31)];
        __syncthreads();
        u64 acc2[4][2];
#pragma unroll
        for (int q = 0; q < 4; q++) { acc2[q][0] = 0ULL; acc2[q][1] = 0ULL; }
        for (int ic = 0; ic < 32; ic++) {
            const float* sip = sbase + ic * 196;
            u64 ra[4], rb[4];
            LOADROW4(ra, sip)
            LOADROW4(rb, sip + 14)
            C2TAPS(0, ra, rb)
            LOADROW4(ra, sip + 28)
            C2TAPS(1, rb, ra)
            LOADROW4(rb, sip + 42)
            C2TAPS(2, ra, rb)
        }
#pragma unroll
        for (int j = 0; j < 2; j++) {
            float l0, h0, l1, h1, l2, h2, l3, h3;
            upk2(acc2[0][j], l0, h0); upk2(acc2[1][j], l1, h1);
            upk2(acc2[2][j], l2, h2); upk2(acc2[3][j], l3, h3);
            int oc = chunk * 32 + octile * 4 + 2 * j;
            float mlo = fmaxf(fmaxf(l0, l1), fmaxf(l2, l3)) + sB[oc];
            float mhi = fmaxf(fmaxf(h0, h1), fmaxf(h2, h3)) + sB[oc + 1];
            outp[oc * 36 + p] = fmaxf(mlo, 0.f);
            outp[(oc + 1) * 36 + p] = fmaxf(mhi, 0.f);
        }
    }
}

// ================= conv3 (64->128) + relu + pool (R15 version, unchanged) ===========
__global__ __launch_bounds__(576) void k_conv3(const float* __restrict__ w,
                                               const float* __restrict__ b) {
    extern __shared__ float sm[];
    float* sIn = sm;               // 8 * 4096 = 32768
    float* sW  = sm + 32768;       // 576 taps * pitch 36 = 20736
    float* sB  = sW + 20736;       // 128
    int blk = blockIdx.x;
    int tid = threadIdx.x;
    for (int i = tid; i < 32768; i += 576) sIn[i] = 0.f;
    if (tid < 128) sB[tid] = b[tid];
    __syncthreads();
    for (int i = tid; i < 8 * 64 * 36; i += 576) {
        int im = i / 2304;
        int r = i - im * 2304;
        int c = r / 36, rr = r - c * 36;
        int y = rr / 6, xx = rr - y * 6;
        sIn[im * 4096 + c * 64 + (y + 1) * 8 + xx + 1] = g_h2[(size_t)(blk * 8 + im) * 2304 + r];
    }
    int im = tid / 72;
    int r = tid - im * 72;
    int octile = r & 7;
    int p = r >> 3;
    int py = p / 3, px = p - py * 3;
    int y0 = 2 * py, x0 = 2 * px;
    const float* sbase = sIn + im * 4096 + y0 * 8 + x0;
    float* outp = g_h3 + (size_t)(blk * 8 + im) * 1152;
    for (int chunk = 0; chunk < 4; chunk++) {
        __syncthreads();
        for (int i = tid; i < 32 * 576; i += 576) {
            int ocl = i / 576, kk = i - ocl * 576;
            sW[kk * 36 + ocl] = w[(chunk * 32 + ocl) * 576 + kk];
        }
        __syncthreads();
        u64 acc2[4][2];
#pragma unroll
        for (int q = 0; q < 4; q++) { acc2[q][0] = 0ULL; acc2[q][1] = 0ULL; }
        for (int ic = 0; ic < 64; ic++) {
            const float* sip = sbase + ic * 64;
            u64 pin[4][4];
#pragma unroll
            for (int dy = 0; dy < 4; dy++) {
                float2 q0 = *reinterpret_cast<const float2*>(sip + dy * 8);
                float2 q1 = *reinterpret_cast<const float2*>(sip + dy * 8 + 2);
                pin[dy][0] = pk2(q0.x, q0.x); pin[dy][1] = pk2(q0.y, q0.y);
                pin[dy][2] = pk2(q1.x, q1.x); pin[dy][3] = pk2(q1.y, q1.y);
            }
#pragma unroll
            for (int k = 0; k < 9; k++) {
                int ky = k / 3, kx = k - ky * 3;
                const u64* wq = reinterpret_cast<const u64*>(sW + (ic * 9 + k) * 36) + octile * 2;
                u64 w01 = wq[0], w23 = wq[1];
                ffma2(acc2[0][0], w01, pin[ky][kx]);         ffma2(acc2[0][1], w23, pin[ky][kx]);
                ffma2(acc2[1][0], w01, pin[ky][kx + 1]);     ffma2(acc2[1][1], w23, pin[ky][kx + 1]);
                ffma2(acc2[2][0], w01, pin[ky + 1][kx]);     ffma2(acc2[2][1], w23, pin[ky + 1][kx]);
                ffma2(acc2[3][0], w01, pin[ky + 1][kx + 1]); ffma2(acc2[3][1], w23, pin[ky + 1][kx + 1]);
            }
        }
#pragma unroll
        for (int j = 0; j < 2; j++) {
            float l0, h0, l1, h1, l2, h2, l3, h3;
            upk2(acc2[0][j], l0, h0); upk2(acc2[1][j], l1, h1);
            upk2(acc2[2][j], l2, h2); upk2(acc2[3][j], l3, h3);
            int oc = chunk * 32 + octile * 4 + 2 * j;
            float mlo = fmaxf(fmaxf(l0, l1), fmaxf(l2, l3)) + sB[oc];
            float mhi = fmaxf(fmaxf(h0, h1), fmaxf(h2, h3)) + sB[oc + 1];
            outp[oc * 9 + p] = fmaxf(mlo, 0.f);
            outp[(oc + 1) * 9 + p] = fmaxf(mhi, 0.f);
        }
    }
}

// ================= enc FC GEMM, split-K x4 over gridDim.z =================
__global__ __launch_bounds__(256) void k_gemm_enc_sk(const float* __restrict__ A,
                                                     const float* __restrict__ Bm) {
    __shared__ float As[16][68];
    __shared__ float Bs[16][68];
    int m0 = blockIdx.x * 64;
    int n0 = blockIdx.y * 64;
    int s  = blockIdx.z;
    int tid = threadIdx.x;
    int lr = tid >> 2;
    int lk = (tid & 3) << 2;
    int tx = tid & 15, ty = tid >> 4;
    u64 acc2[4][2];
#pragma unroll
    for (int i = 0; i < 4; i++) { acc2[i][0] = 0ULL; acc2[i][1] = 0ULL; }
    const float* aPtr = A + (size_t)(m0 + lr) * 1152 + s * 288 + lk;
    const float* bPtr = Bm + (size_t)(n0 + lr) * 1152 + s * 288 + lk;
    for (int k0 = 0; k0 < 288; k0 += 16) {
        float4 av = *(const float4*)(aPtr + k0);
        float4 bv = *(const float4*)(bPtr + k0);
        __syncthreads();
        As[lk + 0][lr] = av.x; As[lk + 1][lr] = av.y; As[lk + 2][lr] = av.z; As[lk + 3][lr] = av.w;
        Bs[lk + 0][lr] = bv.x; Bs[lk + 1][lr] = bv.y; Bs[lk + 2][lr] = bv.z; Bs[lk + 3][lr] = bv.w;
        __syncthreads();
#pragma unroll
        for (int kk = 0; kk < 16; kk++) {
            float4 a = *(const float4*)&As[kk][ty * 4];
            float4 bq = *(const float4*)&Bs[kk][tx * 4];
            u64 pb0 = pk2(bq.x, bq.y), pb1 = pk2(bq.z, bq.w);
            float ar[4] = {a.x, a.y, a.z, a.w};
#pragma unroll
            for (int i = 0; i < 4; i++) {
                u64 pa = pk2(ar[i], ar[i]);
                ffma2(acc2[i][0], pb0, pa);
                ffma2(acc2[i][1], pb1, pa);
            }
        }
    }
    float* outp = g_scores + (size_t)s * BATCH * 128;
#pragma unroll
    for (int i = 0; i < 4; i++) {
        int m = m0 + ty * 4 + i;
        float v[4];
        upk2(acc2[i][0], v[0], v[1]);
        upk2(acc2[i][1], v[2], v[3]);
#pragma unroll
        for (int j = 0; j < 4; j++) {
            int n = n0 + tx * 4 + j;
            outp[(size_t)m * 128 + n] = v[j];
        }
    }
}

// ================= scores GEMM with fused z-reduction + argmin partials ==============
__global__ __launch_bounds__(256) void k_scores(const float* __restrict__ cbm,
                                                const float* __restrict__ encb) {
    __shared__ float As[16][68];
    __shared__ float Bs[16][68];
    __shared__ float sCn[64];
    __shared__ float sBias[128];
    int m0 = blockIdx.x * 64;
    int n0 = blockIdx.y * 64;
    int tid = threadIdx.x;
    if (tid < 64) sCn[tid] = g_cnorm[n0 + tid];
    if (tid < 128) sBias[tid] = encb[tid];
    __syncthreads();
    int lr = tid >> 2;
    int lk = (tid & 3) << 2;
    int tx = tid & 15, ty = tid >> 4;
    u64 acc2[4][2];
#pragma unroll
    for (int i = 0; i < 4; i++) { acc2[i][0] = 0ULL; acc2[i][1] = 0ULL; }
    const size_t S = (size_t)BATCH * 128;
    const float* aPtr = g_scores + (size_t)(m0 + lr) * 128 + lk;
    const float* bPtr = cbm + (size_t)(n0 + lr) * 128 + lk;
    for (int k0 = 0; k0 < 128; k0 += 16) {
        float4 p0 = *(const float4*)(aPtr + k0);
        float4 p1 = *(const float4*)(aPtr + k0 + S);
        float4 p2 = *(const float4*)(aPtr + k0 + 2 * S);
        float4 p3 = *(const float4*)(aPtr + k0 + 3 * S);
        float4 av;
        av.x = (p0.x + p1.x) + (p2.x + p3.x) + sBias[lk + k0 + 0];
        av.y = (p0.y + p1.y) + (p2.y + p3.y) + sBias[lk + k0 + 1];
        av.z = (p0.z + p1.z) + (p2.z + p3.z) + sBias[lk + k0 + 2];
        av.w = (p0.w + p1.w) + (p2.w + p3.w) + sBias[lk + k0 + 3];
        float4 bv = *(const float4*)(bPtr + k0);
        __syncthreads();
        As[lk + 0][lr] = av.x; As[lk + 1][lr] = av.y; As[lk + 2][lr] = av.z; As[lk + 3][lr] = av.w;
        Bs[lk + 0][lr] = bv.x; Bs[lk + 1][lr] = bv.y; Bs[lk + 2][lr] = bv.z; Bs[lk + 3][lr] = bv.w;
        __syncthreads();
#pragma unroll
        for (int kk = 0; kk < 16; kk++) {
            float4 a = *(const float4*)&As[kk][ty * 4];
            float4 bq = *(const float4*)&Bs[kk][tx * 4];
            u64 pb0 = pk2(bq.x, bq.y), pb1 = pk2(bq.z, bq.w);
            float ar[4] = {a.x, a.y, a.z, a.w};
#pragma unroll
            for (int i = 0; i < 4; i++) {
                u64 pa = pk2(ar[i], ar[i]);
                ffma2(acc2[i][0], pb0, pa);
                ffma2(acc2[i][1], pb1, pa);
            }
        }
    }
    int cbi = blockIdx.y;
#pragma unroll
    for (int i = 0; i < 4; i++) {
        int m = m0 + ty * 4 + i;
        float v[4];
        upk2(acc2[i][0], v[0], v[1]);
        upk2(acc2[i][1], v[2], v[3]);
        float best = sCn[tx * 4 + 0] - 2.f * v[0];
        int bidx = n0 + tx * 4 + 0;
#pragma unroll
        for (int j = 1; j < 4; j++) {
            float d = sCn[tx * 4 + j] - 2.f * v[j];
            if (d < best) { best = d; bidx = n0 + tx * 4 + j; }
        }
#pragma unroll
        for (int s = 8; s > 0; s >>= 1) {
            float v2 = __shfl_down_sync(0xffffffffu, best, s, 16);
            int i2 = __shfl_down_sync(0xffffffffu, bidx, s, 16);
            if (v2 < best || (v2 == best && i2 < bidx)) { best = v2; bidx = i2; }
        }
        if (tx == 0) {
            g_pv[(size_t)cbi * BATCH + m] = best;
            g_pi[(size_t)cbi * BATCH + m] = bidx;
        }
    }
}

// ================= final argmin over 16 partials + gather z_q ====================
__global__ __launch_bounds__(256) void k_argmin_final(const float* __restrict__ cb) {
    int tid = threadIdx.x;
    int wid = tid >> 5;
    int lane = tid & 31;
    int img = blockIdx.x * 8 + wid;
    float best = 3.4e38f;
    int bidx = 0x7fffffff;
    if (lane < 16) {
        best = g_pv[(size_t)lane * BATCH + img];
        bidx = g_pi[(size_t)lane * BATCH + img];
    }
#pragma unroll
    for (int s = 8; s > 0; s >>= 1) {
        float v2 = __shfl_down_sync(0xffffffffu, best, s, 16);
        int i2 = __shfl_down_sync(0xffffffffu, bidx, s, 16);
        if (v2 < best || (v2 == best && i2 < bidx)) { best = v2; bidx = i2; }
    }
    int idx = __shfl_sync(0xffffffffu, bidx, 0);
    const float4* src = reinterpret_cast<const float4*>(cb + (size_t)idx * 128);
    float4* dst = reinterpret_cast<float4*>(g_zq + (size_t)img * 128);
    dst[lane] = src[lane];
}

// ================= fused dec_fc+dct1 -> COMPACT d1c [B,64,3,3] =================
__global__ __launch_bounds__(256) void k_fc1() {
    __shared__ float As[16][68];
    __shared__ float Bs[16][68];
    int m0 = blockIdx.x * 64;
    int n0 = blockIdx.y * 64;
    int tid = threadIdx.x;
    int lr = tid >> 2;
    int lk = (tid & 3) << 2;
    int tx = tid & 15, ty = tid >> 4;
    u64 acc2[4][2];
#pragma unroll
    for (int i = 0; i < 4; i++) { acc2[i][0] = 0ULL; acc2[i][1] = 0ULL; }
    const float* aPtr = g_zq + (size_t)(m0 + lr) * 128 + lk;
    const float* bPtr = g_M + (size_t)(n0 + lr) * 128 + lk;
    for (int k0 = 0; k0 < 128; k0 += 16) {
        float4 av = *(const float4*)(aPtr + k0);
        float4 bv = *(const float4*)(bPtr + k0);
        __syncthreads();
        As[lk + 0][lr] = av.x; As[lk + 1][lr] = av.y; As[lk + 2][lr] = av.z; As[lk + 3][lr] = av.w;
        Bs[lk + 0][lr] = bv.x; Bs[lk + 1][lr] = bv.y; Bs[lk + 2][lr] = bv.z; Bs[lk + 3][lr] = bv.w;
        __syncthreads();
#pragma unroll
        for (int kk = 0; kk < 16; kk++) {
            float4 a = *(const float4*)&As[kk][ty * 4];
            float4 bq = *(const float4*)&Bs[kk][tx * 4];
            u64 pb0 = pk2(bq.x, bq.y), pb1 = pk2(bq.z, bq.w);
            float ar[4] = {a.x, a.y, a.z, a.w};
#pragma unroll
            for (int i = 0; i < 4; i++) {
                u64 pa = pk2(ar[i], ar[i]);
                ffma2(acc2[i][0], pb0, pa);
                ffma2(acc2[i][1], pb1, pa);
            }
        }
    }
#pragma unroll
    for (int i = 0; i < 4; i++) {
        int m = m0 + ty * 4 + i;
        float v[4];
        upk2(acc2[i][0], v[0], v[1]);
        upk2(acc2[i][1], v[2], v[3]);
#pragma unroll
        for (int j = 0; j < 4; j++) {
            int n = n0 + tx * 4 + j;
            float val = fmaxf(v[j] + g_cv[n], 0.f);
            g_d1[(size_t)m * 576 + n] = val;
        }
    }
}

// ================= dct2 (64->32) compact conv-transpose (R9 version) =================
__global__ __launch_bounds__(384, 2) void k_dct2(const float* __restrict__ w,
                                                 const float* __restrict__ b) {
    extern __shared__ float sm[];
    float* sIn = sm;                // 8 * 576 = 4608
    float* sW  = sm + 4608;         // 576 taps * pitch 36 = 20736 (flipped)
    float* sB  = sW + 20736;        // 32
    int blk = blockIdx.x;           // 1024
    int tid = threadIdx.x;
    for (int i = tid; i < 8 * 576; i += 384)
        sIn[i] = g_d1[(size_t)blk * 8 * 576 + i];
    for (int i = tid; i < 64 * 288; i += 384) {
        int ic = i / 288, r2 = i - ic * 288;
        int oc = r2 / 9, g = r2 - oc * 9;
        sW[(ic * 9 + 8 - g) * 36 + oc] = w[i];
    }
    if (tid < 32) sB[tid] = b[tid];
    __syncthreads();
    int im = tid / 48;
    int r = tid - im * 48;
    int octile = r & 7;
    int y = r >> 3;
    int sy = y & 1;
    int rtop = (y - 1) >> 1;
    const float* sip = sIn + im * 576;
    u64 acc2[6][2];
#pragma unroll
    for (int xq = 0; xq < 6; xq++) { acc2[xq][0] = 0ULL; acc2[xq][1] = 0ULL; }
    for (int ic = 0; ic < 64; ic++) {
        const float* ch = sip + ic * 9;
        u64 pinr[2][5];
#pragma unroll
        for (int rr = 0; rr < 2; rr++) {
            int row = rtop + rr;
            bool v = (row >= 0) && (row < 3);
            pinr[rr][0] = 0ULL;
            pinr[rr][4] = 0ULL;
#pragma unroll
            for (int c = 0; c < 3; c++) {
                float f = v ? ch[row * 3 + c] : 0.f;
                pinr[rr][c + 1] = pk2(f, f);
            }
        }
        const u64* rowp[3];
        rowp[0] = pinr[0];
        rowp[1] = sy ? pinr[0] : pinr[1];
        rowp[2] = pinr[1];
#pragma unroll
        for (int ky = 0; ky < 3; ky++) {
            const u64* prow = rowp[ky];
#pragma unroll
            for (int kx = 0; kx < 3; kx++) {
                const u64* wq = reinterpret_cast<const u64*>(sW + (ic * 9 + ky * 3 + kx) * 36) + octile * 2;
                u64 w01 = wq[0], w23 = wq[1];
#pragma unroll
                for (int xq = 0; xq < 6; xq++) {
                    int c = ((xq + kx - 1) >> 1) + 1;
                    ffma2(acc2[xq][0], w01, prow[c]);
                    ffma2(acc2[xq][1], w23, prow[c]);
                }
            }
        }
    }
#pragma unroll
    for (int j = 0; j < 2; j++) {
        int oc = octile * 4 + 2 * j;
        float blo = sB[oc], bhi = sB[oc + 1];
        float* olo = g_d2 + ((size_t)(blk * 8 + im) * 32 + oc) * 36 + y * 6;
        float* ohi = olo + 36;
#pragma unroll
        for (int xq = 0; xq < 6; xq++) {
            float vl, vh;
            upk2(acc2[xq][j], vl, vh);
            olo[xq] = fmaxf(vl + blo, 0.f);
            ohi[xq] = fmaxf(vh + bhi, 0.f);
        }
    }
}

// ================= dct3 (32->1) compact conv-transpose + up2 -> out (R9 version) =====
__global__ __launch_bounds__(192) void k_dct3(const float* __restrict__ w,
                                              const float* __restrict__ b,
                                              float* __restrict__ out) {
    extern __shared__ float sm[];
    float* sIn = sm;                // 8 * 1152 = 9216
    float* sW  = sm + 9216;         // 288
    int blk = blockIdx.x;           // 1024
    int tid = threadIdx.x;
    for (int i = tid; i < 8 * 1152; i += 192)
        sIn[i] = g_d2[(size_t)blk * 8 * 1152 + i];
    for (int i = tid; i < 288; i += 192) {
        int ic = i / 9, k = i - ic * 9;
        sW[ic * 9 + k] = w[ic * 9 + (8 - k)];
    }
    __syncthreads();
    float b0 = b[0];
    int im = tid / 24;
    int r = tid - im * 24;
    int y = r >> 1;
    int xh2 = (r & 1) * 3;
    int xh = (r & 1) * 6;
    int sy = y & 1;
    int rtop = (y - 1) >> 1;
    const float* sip = sIn + im * 1152;
    float acc[6];
#pragma unroll
    for (int xq = 0; xq < 6; xq++) acc[xq] = 0.f;
    for (int ic = 0; ic < 32; ic++) {
        const float* ch = sip + ic * 36;
        float pinr[2][8];
#pragma unroll
        for (int rr = 0; rr < 2; rr++) {
            int row = rtop + rr;
            bool v = (row >= 0) && (row < 6);
            pinr[rr][0] = 0.f;
            pinr[rr][7] = 0.f;
#pragma unroll
            for (int c = 0; c < 6; c++)
                pinr[rr][c + 1] = v ? ch[row * 6 + c] : 0.f;
        }
        const float* rowp[3];
        rowp[0] = pinr[0];
        rowp[1] = sy ? pinr[0] : pinr[1];
        rowp[2] = pinr[1];
#pragma unroll
        for (int ky = 0; ky < 3; ky++) {
            const float* prow = rowp[ky];
            float w3[3];
#pragma unroll
            for (int kx = 0; kx < 3; kx++) w3[kx] = sW[ic * 9 + ky * 3 + kx];
#pragma unroll
            for (int xq = 0; xq < 6; xq++)
#pragma unroll
                for (int kx = 0; kx < 3; kx++) {
                    int c = xh2 + ((xq + kx - 1) >> 1) + 1;
                    acc[xq] = fmaf(prow[c], w3[kx], acc[xq]);
                }
        }
    }
    float* o = out + (size_t)(blk * 8 + im) * 576;
#pragma unroll
    for (int xq = 0; xq < 6; xq++) {
        float v = fmaxf(acc[xq] + b0, 0.f);
        int gx = xh + xq;
        int rb = (2 * y) * 24 + 2 * gx;
        o[rb] = v; o[rb + 1] = v; o[rb + 24] = v; o[rb + 25] = v;
    }
}

// ================= launcher =================
extern "C" void kernel_launch(void* const* d_in, const int* in_sizes, int n_in,
                              void* d_out, int out_size) {
    (void)in_sizes; (void)n_in; (void)out_size;
    const float* x    = (const float*)d_in[0];
    const float* c1w  = (const float*)d_in[1];
    const float* c1b  = (const float*)d_in[2];
    const float* c2w  = (const float*)d_in[3];
    const float* c2b  = (const float*)d_in[4];
    const float* c3w  = (const float*)d_in[5];
    const float* c3b  = (const float*)d_in[6];
    const float* encw = (const float*)d_in[7];
    const float* encb = (const float*)d_in[8];
    const float* cb   = (const float*)d_in[9];
    const float* decw = (const float*)d_in[10];
    const float* decb = (const float*)d_in[11];
    const float* d1w  = (const float*)d_in[12];
    const float* d1b  = (const float*)d_in[13];
    const float* d2w  = (const float*)d_in[14];
    const float* d2b  = (const float*)d_in[15];
    const float* d3w  = (const float*)d_in[16];
    const float* d3b  = (const float*)d_in[17];
    float* out = (float*)d_out;

    cudaFuncSetAttribute(k_conv2, cudaFuncAttributeMaxDynamicSharedMemorySize, 87296);
    cudaFuncSetAttribute(k_conv3, cudaFuncAttributeMaxDynamicSharedMemorySize, 214528);
    cudaFuncSetAttribute(k_dct2,  cudaFuncAttributeMaxDynamicSharedMemorySize, 101504);
    cudaFuncSetAttribute(k_dct3,  cudaFuncAttributeMaxDynamicSharedMemorySize, 38016);

    float* p_h3;
    cudaGetSymbolAddress((void**)&p_h3, g_h3);

    // conv1 + prep fused in one grid
    k_conv1<<<BATCH + 72, 256>>>(x, c1w, c1b, c2w, cb);
    // conv2 + buildM fused in one grid
    k_conv2<<<BATCH / 2 + 576, 576, 87296>>>(c2b, d1w, d1b, decw, decb);
    k_conv3<<<BATCH / 8, 576, 214528>>>(c3w, c3b);
    k_gemm_enc_sk<<<dim3(BATCH / 64, 2, 4), 256>>>(p_h3, encw);
    k_scores<<<dim3(BATCH / 64, 16), 256>>>(cb, encb);
    k_argmin_final<<<BATCH / 8, 256>>>(cb);
    k_fc1<<<dim3(BATCH / 64, 9), 256>>>();
    k_dct2<<<BATCH / 8, 384, 101504>>>(d2w, d2b);
    k_dct3<<<BATCH / 8, 192, 38016>>>(d3w, d3b, out);
}